// round 5
// baseline (speedup 1.0000x reference)
#include <cuda_runtime.h>
#include <cstdint>
#include <math_constants.h>

#define BB 8
#define DD 256
#define NK 4096
#define TQ 1024
#define SC 0.0625f
#define EPS 0.04f
#define CAP 32

__device__ int g_cnt[BB * TQ];
__device__ int g_cand[BB * TQ * CAP];

// tf32 round-to-nearest of an fp32, returned as float bit pattern
__device__ __forceinline__ float tf32f(float x) {
    uint32_t u;
    asm("cvt.rna.tf32.f32 %0, %1;" : "=r"(u) : "f"(x));
    return __uint_as_float(u);
}

__device__ __forceinline__ void mma8(float* c, const uint32_t* a, const uint32_t* b) {
    asm volatile(
        "mma.sync.aligned.m16n8k8.row.col.f32.tf32.tf32.f32 "
        "{%0,%1,%2,%3}, {%4,%5,%6,%7}, {%8,%9}, {%0,%1,%2,%3};"
        : "+f"(c[0]), "+f"(c[1]), "+f"(c[2]), "+f"(c[3])
        : "r"(a[0]), "r"(a[1]), "r"(a[2]), "r"(a[3]), "r"(b[0]), "r"(b[1]));
}

// ---------------------------------------------------------------------------
// GEMM1: S[n][t] = SC * sum_d K[d][n] * Q[d][t]   (tf32 mma.sync)
// CTA tile 128(n) x 128(t), k-chunk 32 over d. 8 warps: 2(n) x 4(t).
// ---------------------------------------------------------------------------
__global__ void __launch_bounds__(256) gemm1(const float* __restrict__ K,
                                             const float* __restrict__ Q,
                                             float* __restrict__ S) {
    __shared__ float Ks[32][132];   // [d][n]
    __shared__ float Qs[32][132];   // [d][t]

    const int b = blockIdx.z, n0 = blockIdx.y * 128, t0 = blockIdx.x * 128;
    const int tid = threadIdx.x, lane = tid & 31, warp = tid >> 5;
    const int wy = warp >> 2, wx = warp & 3;       // warp tile: 64(n) x 32(t)
    const int tig = lane & 3, grp = lane >> 2;

    const float* Kb = K + (size_t)b * DD * NK;
    const float* Qb = Q + (size_t)b * DD * TQ;

    float acc[4][4][4] = {};
    float4 kreg[4], qreg[4];

#pragma unroll
    for (int p = 0; p < 4; p++) {
        int fl = tid + p * 256, r = fl >> 5, c = (fl & 31) * 4;
        kreg[p] = *(const float4*)&Kb[(size_t)r * NK + n0 + c];
        qreg[p] = *(const float4*)&Qb[(size_t)r * TQ + t0 + c];
    }

    for (int ch = 0; ch < 8; ch++) {
#pragma unroll
        for (int p = 0; p < 4; p++) {
            int fl = tid + p * 256, r = fl >> 5, c = (fl & 31) * 4;
            Ks[r][c + 0] = tf32f(kreg[p].x); Ks[r][c + 1] = tf32f(kreg[p].y);
            Ks[r][c + 2] = tf32f(kreg[p].z); Ks[r][c + 3] = tf32f(kreg[p].w);
            Qs[r][c + 0] = tf32f(qreg[p].x); Qs[r][c + 1] = tf32f(qreg[p].y);
            Qs[r][c + 2] = tf32f(qreg[p].z); Qs[r][c + 3] = tf32f(qreg[p].w);
        }
        __syncthreads();
        if (ch < 7) {
            const int k0 = (ch + 1) * 32;
#pragma unroll
            for (int p = 0; p < 4; p++) {
                int fl = tid + p * 256, r = fl >> 5, c = (fl & 31) * 4;
                kreg[p] = *(const float4*)&Kb[(size_t)(k0 + r) * NK + n0 + c];
                qreg[p] = *(const float4*)&Qb[(size_t)(k0 + r) * TQ + t0 + c];
            }
        }
#pragma unroll
        for (int kk = 0; kk < 4; kk++) {
            uint32_t af[4][4], bf[4][2];
#pragma unroll
            for (int mi = 0; mi < 4; mi++) {
                int rb = wy * 64 + mi * 16 + grp;
                af[mi][0] = __float_as_uint(Ks[kk * 8 + tig][rb]);
                af[mi][1] = __float_as_uint(Ks[kk * 8 + tig][rb + 8]);
                af[mi][2] = __float_as_uint(Ks[kk * 8 + tig + 4][rb]);
                af[mi][3] = __float_as_uint(Ks[kk * 8 + tig + 4][rb + 8]);
            }
#pragma unroll
            for (int nj = 0; nj < 4; nj++) {
                int cb = wx * 32 + nj * 8 + grp;
                bf[nj][0] = __float_as_uint(Qs[kk * 8 + tig][cb]);
                bf[nj][1] = __float_as_uint(Qs[kk * 8 + tig + 4][cb]);
            }
#pragma unroll
            for (int mi = 0; mi < 4; mi++)
#pragma unroll
                for (int nj = 0; nj < 4; nj++)
                    mma8(acc[mi][nj], af[mi], bf[nj]);
        }
        __syncthreads();
    }

    float* Sb = S + (size_t)b * NK * TQ;
#pragma unroll
    for (int mi = 0; mi < 4; mi++)
#pragma unroll
        for (int nj = 0; nj < 4; nj++) {
            int rg = n0 + wy * 64 + mi * 16 + grp;
            int cg = t0 + wx * 32 + nj * 8 + tig * 2;
            float2 v0 = {acc[mi][nj][0] * SC, acc[mi][nj][1] * SC};
            float2 v1 = {acc[mi][nj][2] * SC, acc[mi][nj][3] * SC};
            *(float2*)&Sb[(size_t)rg * TQ + cg] = v0;
            *(float2*)&Sb[(size_t)(rg + 8) * TQ + cg] = v1;
        }
}

// ---------------------------------------------------------------------------
// GEMM2: R[d][t] = sum_n V[d][n] * A[n][t]   (tf32 mma.sync)
// CTA tile 128(d) x 128(t), k-chunk 32 over n.
// ---------------------------------------------------------------------------
__global__ void __launch_bounds__(256) gemm2(const float* __restrict__ V,
                                             const float* __restrict__ A,
                                             float* __restrict__ R) {
    __shared__ float Vs[128][36];   // [d][n]
    __shared__ float As[32][132];   // [n][t]

    const int b = blockIdx.z, d0 = blockIdx.y * 128, t0 = blockIdx.x * 128;
    const int tid = threadIdx.x, lane = tid & 31, warp = tid >> 5;
    const int wy = warp >> 2, wx = warp & 3;
    const int tig = lane & 3, grp = lane >> 2;

    const float* Vb = V + (size_t)b * DD * NK + (size_t)d0 * NK;
    const float* Ab = A + (size_t)b * NK * TQ;

    float acc[4][4][4] = {};
    float4 vreg[4], areg[4];

#pragma unroll
    for (int p = 0; p < 4; p++) {
        int fl = tid + p * 256;
        int rv = fl >> 3, cv = (fl & 7) * 4;
        vreg[p] = *(const float4*)&Vb[(size_t)rv * NK + cv];
        int ra = fl >> 5, ca = (fl & 31) * 4;
        areg[p] = *(const float4*)&Ab[(size_t)ra * TQ + t0 + ca];
    }

    for (int ch = 0; ch < 128; ch++) {
#pragma unroll
        for (int p = 0; p < 4; p++) {
            int fl = tid + p * 256;
            int rv = fl >> 3, cv = (fl & 7) * 4;
            Vs[rv][cv + 0] = tf32f(vreg[p].x); Vs[rv][cv + 1] = tf32f(vreg[p].y);
            Vs[rv][cv + 2] = tf32f(vreg[p].z); Vs[rv][cv + 3] = tf32f(vreg[p].w);
            int ra = fl >> 5, ca = (fl & 31) * 4;
            As[ra][ca + 0] = tf32f(areg[p].x); As[ra][ca + 1] = tf32f(areg[p].y);
            As[ra][ca + 2] = tf32f(areg[p].z); As[ra][ca + 3] = tf32f(areg[p].w);
        }
        __syncthreads();
        if (ch < 127) {
            const int k0 = (ch + 1) * 32;
#pragma unroll
            for (int p = 0; p < 4; p++) {
                int fl = tid + p * 256;
                int rv = fl >> 3, cv = (fl & 7) * 4;
                vreg[p] = *(const float4*)&Vb[(size_t)rv * NK + k0 + cv];
                int ra = fl >> 5, ca = (fl & 31) * 4;
                areg[p] = *(const float4*)&Ab[(size_t)(k0 + ra) * TQ + t0 + ca];
            }
        }
#pragma unroll
        for (int kk = 0; kk < 4; kk++) {
            uint32_t af[4][4], bf[4][2];
#pragma unroll
            for (int mi = 0; mi < 4; mi++) {
                int rb = wy * 64 + mi * 16 + grp;
                af[mi][0] = __float_as_uint(Vs[rb][kk * 8 + tig]);
                af[mi][1] = __float_as_uint(Vs[rb + 8][kk * 8 + tig]);
                af[mi][2] = __float_as_uint(Vs[rb][kk * 8 + tig + 4]);
                af[mi][3] = __float_as_uint(Vs[rb + 8][kk * 8 + tig + 4]);
            }
#pragma unroll
            for (int nj = 0; nj < 4; nj++) {
                int cb = wx * 32 + nj * 8 + grp;
                bf[nj][0] = __float_as_uint(As[kk * 8 + tig][cb]);
                bf[nj][1] = __float_as_uint(As[kk * 8 + tig + 4][cb]);
            }
#pragma unroll
            for (int mi = 0; mi < 4; mi++)
#pragma unroll
                for (int nj = 0; nj < 4; nj++)
                    mma8(acc[mi][nj], af[mi], bf[nj]);
        }
        __syncthreads();
    }

    float* Rb = R + (size_t)b * (2 * DD) * TQ;
#pragma unroll
    for (int mi = 0; mi < 4; mi++)
#pragma unroll
        for (int nj = 0; nj < 4; nj++) {
            int rg = d0 + wy * 64 + mi * 16 + grp;
            int cg = t0 + wx * 32 + nj * 8 + tig * 2;
            float2 v0 = {acc[mi][nj][0], acc[mi][nj][1]};
            float2 v1 = {acc[mi][nj][2], acc[mi][nj][3]};
            *(float2*)&Rb[(size_t)rg * TQ + cg] = v0;
            *(float2*)&Rb[(size_t)(rg + 8) * TQ + cg] = v1;
        }
}

// ---------------------------------------------------------------------------
// Softmax over n per (b,t) column, in place; collects argmax candidates
// (score >= max - EPS) for exact refinement.
// ---------------------------------------------------------------------------
__global__ void softmax_cand(float* __restrict__ A) {
    const int b = blockIdx.y;
    const int tx = threadIdx.x;      // 0..31 (t lane)
    const int ty = threadIdx.y;      // 0..15 (n partition)
    const int t = blockIdx.x * 32 + tx;

    float* Ab = A + (size_t)b * NK * TQ + t;

    __shared__ float sm[16][33];
    __shared__ float ss[16][33];
    __shared__ int scnt[32];
    __shared__ int scand[32][CAP];

    if (ty == 0) scnt[tx] = 0;

    float m = -3.0e38f;
#pragma unroll 4
    for (int n = ty; n < NK; n += 16) {
        float s = Ab[(size_t)n * TQ];
        if (s > m) m = s;
    }
    sm[ty][tx] = m;
    __syncthreads();
    if (ty == 0) {
#pragma unroll
        for (int r = 1; r < 16; r++) m = fmaxf(m, sm[r][tx]);
        sm[0][tx] = m;
    }
    __syncthreads();
    m = sm[0][tx];

    const float thr = m - EPS;
    float sum = 0.0f;
#pragma unroll 4
    for (int n = ty; n < NK; n += 16) {
        float s = Ab[(size_t)n * TQ];
        sum += __expf(s - m);
        if (s >= thr) {
            int p = atomicAdd(&scnt[tx], 1);
            if (p < CAP) scand[tx][p] = n;
        }
    }
    ss[ty][tx] = sum;
    __syncthreads();
    if (ty == 0) {
#pragma unroll
        for (int r = 1; r < 16; r++) sum += ss[r][tx];
        ss[0][tx] = 1.0f / sum;
    }
    __syncthreads();
    const float inv = ss[0][tx];

#pragma unroll 4
    for (int n = ty; n < NK; n += 16) {
        size_t o = (size_t)n * TQ;
        Ab[o] = __expf(Ab[o] - m) * inv;
    }

    if (ty == 0) {
        int col = b * TQ + t;
        int c = min(scnt[tx], CAP);
        g_cnt[col] = c;
        for (int i = 0; i < c; i++) g_cand[(size_t)col * CAP + i] = scand[tx][i];
    }
}

// ---------------------------------------------------------------------------
// Exact fp32 argmax over candidate set. One warp per (b,t) column.
// ---------------------------------------------------------------------------
__global__ void refine(const float* __restrict__ K, const float* __restrict__ Q,
                       float* __restrict__ Mx) {
    const int col = blockIdx.x * 8 + (threadIdx.x >> 5);
    const int lane = threadIdx.x & 31;
    const int b = col >> 10, t = col & 1023;

    const int cnt = min(g_cnt[col], CAP);
    const float* Kb = K + (size_t)b * DD * NK;
    const float* Qb = Q + (size_t)b * DD * TQ;

    int bi;
    if (cnt == 1) {
        bi = g_cand[(size_t)col * CAP];
    } else {
        float bs = -CUDART_INF_F;
        bi = 0x7fffffff;
        for (int c = 0; c < cnt; c++) {
            int n = g_cand[(size_t)col * CAP + c];
            float s = 0.0f;
#pragma unroll
            for (int d = lane; d < DD; d += 32)
                s += Kb[(size_t)d * NK + n] * Qb[(size_t)d * TQ + t];
#pragma unroll
            for (int o = 16; o > 0; o >>= 1)
                s += __shfl_xor_sync(0xFFFFFFFFu, s, o);
            if (s > bs || (s == bs && n < bi)) { bs = s; bi = n; }
        }
    }
    if (lane == 0) Mx[col] = (float)bi;
}

// ---------------------------------------------------------------------------
__global__ void copy_q(const float* __restrict__ Q, float* __restrict__ O) {
    const size_t per = (size_t)DD * TQ;
    const size_t total = (size_t)BB * per;
    size_t i = (size_t)blockIdx.x * blockDim.x + threadIdx.x;
    const size_t stride = (size_t)gridDim.x * blockDim.x;
    for (size_t e = i * 4; e < total; e += stride * 4) {
        size_t b = e / per;
        size_t r = e - b * per;
        float4 v = *(const float4*)&Q[e];
        *(float4*)&O[b * (size_t)(2 * DD) * TQ + per + r] = v;
    }
}

extern "C" void kernel_launch(void* const* d_in, const int* in_sizes, int n_in,
                              void* d_out, int out_size) {
    const float* K = (const float*)d_in[0];
    const float* V = (const float*)d_in[1];
    const float* Q = (const float*)d_in[2];
    float* out = (float*)d_out;

    float* R = out;
    float* A = out + (size_t)BB * 2 * DD * TQ;
    float* MX = A + (size_t)BB * NK * TQ;

    gemm1<<<dim3(TQ / 128, NK / 128, BB), 256>>>(K, Q, A);
    softmax_cand<<<dim3(TQ / 32, BB), dim3(32, 16)>>>(A);
    refine<<<(BB * TQ) / 8, 256>>>(K, Q, MX);
    gemm2<<<dim3(TQ / 128, DD / 128, BB), 256>>>(V, A, R);
    copy_q<<<512, 256>>>(Q, R);
}

// round 6
// speedup vs baseline: 1.0005x; 1.0005x over previous
#include <cuda_runtime.h>
#include <cstdint>
#include <math_constants.h>

#define BB 8
#define DD 256
#define NK 4096
#define TQ 1024
#define SC 0.0625f
#define EPS 0.04f
#define CAP 32

__device__ int g_cnt[BB * TQ];
__device__ int g_cand[BB * TQ * CAP];

// tf32 round-to-nearest of an fp32, returned as float bit pattern
__device__ __forceinline__ float tf32f(float x) {
    uint32_t u;
    asm("cvt.rna.tf32.f32 %0, %1;" : "=r"(u) : "f"(x));
    return __uint_as_float(u);
}

__device__ __forceinline__ void mma8(float* c, const uint32_t* a, const uint32_t* b) {
    asm volatile(
        "mma.sync.aligned.m16n8k8.row.col.f32.tf32.tf32.f32 "
        "{%0,%1,%2,%3}, {%4,%5,%6,%7}, {%8,%9}, {%0,%1,%2,%3};"
        : "+f"(c[0]), "+f"(c[1]), "+f"(c[2]), "+f"(c[3])
        : "r"(a[0]), "r"(a[1]), "r"(a[2]), "r"(a[3]), "r"(b[0]), "r"(b[1]));
}

// ---------------------------------------------------------------------------
// GEMM1: S[n][t] = SC * sum_d K[d][n] * Q[d][t]   (tf32 mma.sync)
// CTA tile 128(n) x 128(t), k-chunk 32 over d. 8 warps: 2(n) x 4(t).
// ---------------------------------------------------------------------------
__global__ void __launch_bounds__(256) gemm1(const float* __restrict__ K,
                                             const float* __restrict__ Q,
                                             float* __restrict__ S) {
    __shared__ float Ks[32][132];   // [d][n]
    __shared__ float Qs[32][132];   // [d][t]

    const int b = blockIdx.z, n0 = blockIdx.y * 128, t0 = blockIdx.x * 128;
    const int tid = threadIdx.x, lane = tid & 31, warp = tid >> 5;
    const int wy = warp >> 2, wx = warp & 3;       // warp tile: 64(n) x 32(t)
    const int tig = lane & 3, grp = lane >> 2;

    const float* Kb = K + (size_t)b * DD * NK;
    const float* Qb = Q + (size_t)b * DD * TQ;

    float acc[4][4][4] = {};
    float4 kreg[4], qreg[4];

#pragma unroll
    for (int p = 0; p < 4; p++) {
        int fl = tid + p * 256, r = fl >> 5, c = (fl & 31) * 4;
        kreg[p] = *(const float4*)&Kb[(size_t)r * NK + n0 + c];
        qreg[p] = *(const float4*)&Qb[(size_t)r * TQ + t0 + c];
    }

    for (int ch = 0; ch < 8; ch++) {
#pragma unroll
        for (int p = 0; p < 4; p++) {
            int fl = tid + p * 256, r = fl >> 5, c = (fl & 31) * 4;
            Ks[r][c + 0] = tf32f(kreg[p].x); Ks[r][c + 1] = tf32f(kreg[p].y);
            Ks[r][c + 2] = tf32f(kreg[p].z); Ks[r][c + 3] = tf32f(kreg[p].w);
            Qs[r][c + 0] = tf32f(qreg[p].x); Qs[r][c + 1] = tf32f(qreg[p].y);
            Qs[r][c + 2] = tf32f(qreg[p].z); Qs[r][c + 3] = tf32f(qreg[p].w);
        }
        __syncthreads();
        if (ch < 7) {
            const int k0 = (ch + 1) * 32;
#pragma unroll
            for (int p = 0; p < 4; p++) {
                int fl = tid + p * 256, r = fl >> 5, c = (fl & 31) * 4;
                kreg[p] = *(const float4*)&Kb[(size_t)(k0 + r) * NK + n0 + c];
                qreg[p] = *(const float4*)&Qb[(size_t)(k0 + r) * TQ + t0 + c];
            }
        }
#pragma unroll
        for (int kk = 0; kk < 4; kk++) {
            uint32_t af[4][4], bf[4][2];
#pragma unroll
            for (int mi = 0; mi < 4; mi++) {
                int rb = wy * 64 + mi * 16 + grp;
                af[mi][0] = __float_as_uint(Ks[kk * 8 + tig][rb]);
                af[mi][1] = __float_as_uint(Ks[kk * 8 + tig][rb + 8]);
                af[mi][2] = __float_as_uint(Ks[kk * 8 + tig + 4][rb]);
                af[mi][3] = __float_as_uint(Ks[kk * 8 + tig + 4][rb + 8]);
            }
#pragma unroll
            for (int nj = 0; nj < 4; nj++) {
                int cb = wx * 32 + nj * 8 + grp;
                bf[nj][0] = __float_as_uint(Qs[kk * 8 + tig][cb]);
                bf[nj][1] = __float_as_uint(Qs[kk * 8 + tig + 4][cb]);
            }
#pragma unroll
            for (int mi = 0; mi < 4; mi++)
#pragma unroll
                for (int nj = 0; nj < 4; nj++)
                    mma8(acc[mi][nj], af[mi], bf[nj]);
        }
        __syncthreads();
    }

    float* Sb = S + (size_t)b * NK * TQ;
#pragma unroll
    for (int mi = 0; mi < 4; mi++)
#pragma unroll
        for (int nj = 0; nj < 4; nj++) {
            int rg = n0 + wy * 64 + mi * 16 + grp;
            int cg = t0 + wx * 32 + nj * 8 + tig * 2;
            float2 v0 = {acc[mi][nj][0] * SC, acc[mi][nj][1] * SC};
            float2 v1 = {acc[mi][nj][2] * SC, acc[mi][nj][3] * SC};
            *(float2*)&Sb[(size_t)rg * TQ + cg] = v0;
            *(float2*)&Sb[(size_t)(rg + 8) * TQ + cg] = v1;
        }
}

// ---------------------------------------------------------------------------
// GEMM2: R[d][t] = sum_n V[d][n] * A[n][t]   (tf32 mma.sync)
// CTA tile 128(d) x 128(t), k-chunk 32 over n.
// ---------------------------------------------------------------------------
__global__ void __launch_bounds__(256) gemm2(const float* __restrict__ V,
                                             const float* __restrict__ A,
                                             float* __restrict__ R) {
    __shared__ float Vs[128][36];   // [d][n]
    __shared__ float As[32][132];   // [n][t]

    const int b = blockIdx.z, d0 = blockIdx.y * 128, t0 = blockIdx.x * 128;
    const int tid = threadIdx.x, lane = tid & 31, warp = tid >> 5;
    const int wy = warp >> 2, wx = warp & 3;
    const int tig = lane & 3, grp = lane >> 2;

    const float* Vb = V + (size_t)b * DD * NK + (size_t)d0 * NK;
    const float* Ab = A + (size_t)b * NK * TQ;

    float acc[4][4][4] = {};
    float4 vreg[4], areg[4];

#pragma unroll
    for (int p = 0; p < 4; p++) {
        int fl = tid + p * 256;
        int rv = fl >> 3, cv = (fl & 7) * 4;
        vreg[p] = *(const float4*)&Vb[(size_t)rv * NK + cv];
        int ra = fl >> 5, ca = (fl & 31) * 4;
        areg[p] = *(const float4*)&Ab[(size_t)ra * TQ + t0 + ca];
    }

    for (int ch = 0; ch < 128; ch++) {
#pragma unroll
        for (int p = 0; p < 4; p++) {
            int fl = tid + p * 256;
            int rv = fl >> 3, cv = (fl & 7) * 4;
            Vs[rv][cv + 0] = tf32f(vreg[p].x); Vs[rv][cv + 1] = tf32f(vreg[p].y);
            Vs[rv][cv + 2] = tf32f(vreg[p].z); Vs[rv][cv + 3] = tf32f(vreg[p].w);
            int ra = fl >> 5, ca = (fl & 31) * 4;
            As[ra][ca + 0] = tf32f(areg[p].x); As[ra][ca + 1] = tf32f(areg[p].y);
            As[ra][ca + 2] = tf32f(areg[p].z); As[ra][ca + 3] = tf32f(areg[p].w);
        }
        __syncthreads();
        if (ch < 127) {
            const int k0 = (ch + 1) * 32;
#pragma unroll
            for (int p = 0; p < 4; p++) {
                int fl = tid + p * 256;
                int rv = fl >> 3, cv = (fl & 7) * 4;
                vreg[p] = *(const float4*)&Vb[(size_t)rv * NK + k0 + cv];
                int ra = fl >> 5, ca = (fl & 31) * 4;
                areg[p] = *(const float4*)&Ab[(size_t)(k0 + ra) * TQ + t0 + ca];
            }
        }
#pragma unroll
        for (int kk = 0; kk < 4; kk++) {
            uint32_t af[4][4], bf[4][2];
#pragma unroll
            for (int mi = 0; mi < 4; mi++) {
                int rb = wy * 64 + mi * 16 + grp;
                af[mi][0] = __float_as_uint(Vs[rb][kk * 8 + tig]);
                af[mi][1] = __float_as_uint(Vs[rb + 8][kk * 8 + tig]);
                af[mi][2] = __float_as_uint(Vs[rb][kk * 8 + tig + 4]);
                af[mi][3] = __float_as_uint(Vs[rb + 8][kk * 8 + tig + 4]);
            }
#pragma unroll
            for (int nj = 0; nj < 4; nj++) {
                int cb = wx * 32 + nj * 8 + grp;
                bf[nj][0] = __float_as_uint(As[kk * 8 + tig][cb]);
                bf[nj][1] = __float_as_uint(As[kk * 8 + tig + 4][cb]);
            }
#pragma unroll
            for (int mi = 0; mi < 4; mi++)
#pragma unroll
                for (int nj = 0; nj < 4; nj++)
                    mma8(acc[mi][nj], af[mi], bf[nj]);
        }
        __syncthreads();
    }

    float* Rb = R + (size_t)b * (2 * DD) * TQ;
#pragma unroll
    for (int mi = 0; mi < 4; mi++)
#pragma unroll
        for (int nj = 0; nj < 4; nj++) {
            int rg = d0 + wy * 64 + mi * 16 + grp;
            int cg = t0 + wx * 32 + nj * 8 + tig * 2;
            float2 v0 = {acc[mi][nj][0], acc[mi][nj][1]};
            float2 v1 = {acc[mi][nj][2], acc[mi][nj][3]};
            *(float2*)&Rb[(size_t)rg * TQ + cg] = v0;
            *(float2*)&Rb[(size_t)(rg + 8) * TQ + cg] = v1;
        }
}

// ---------------------------------------------------------------------------
// Softmax over n per (b,t) column, in place; collects argmax candidates
// (score >= max - EPS) for exact refinement.
// ---------------------------------------------------------------------------
__global__ void softmax_cand(float* __restrict__ A) {
    const int b = blockIdx.y;
    const int tx = threadIdx.x;      // 0..31 (t lane)
    const int ty = threadIdx.y;      // 0..15 (n partition)
    const int t = blockIdx.x * 32 + tx;

    float* Ab = A + (size_t)b * NK * TQ + t;

    __shared__ float sm[16][33];
    __shared__ float ss[16][33];
    __shared__ int scnt[32];
    __shared__ int scand[32][CAP];

    if (ty == 0) scnt[tx] = 0;

    float m = -3.0e38f;
#pragma unroll 4
    for (int n = ty; n < NK; n += 16) {
        float s = Ab[(size_t)n * TQ];
        if (s > m) m = s;
    }
    sm[ty][tx] = m;
    __syncthreads();
    if (ty == 0) {
#pragma unroll
        for (int r = 1; r < 16; r++) m = fmaxf(m, sm[r][tx]);
        sm[0][tx] = m;
    }
    __syncthreads();
    m = sm[0][tx];

    const float thr = m - EPS;
    float sum = 0.0f;
#pragma unroll 4
    for (int n = ty; n < NK; n += 16) {
        float s = Ab[(size_t)n * TQ];
        sum += __expf(s - m);
        if (s >= thr) {
            int p = atomicAdd(&scnt[tx], 1);
            if (p < CAP) scand[tx][p] = n;
        }
    }
    ss[ty][tx] = sum;
    __syncthreads();
    if (ty == 0) {
#pragma unroll
        for (int r = 1; r < 16; r++) sum += ss[r][tx];
        ss[0][tx] = 1.0f / sum;
    }
    __syncthreads();
    const float inv = ss[0][tx];

#pragma unroll 4
    for (int n = ty; n < NK; n += 16) {
        size_t o = (size_t)n * TQ;
        Ab[o] = __expf(Ab[o] - m) * inv;
    }

    if (ty == 0) {
        int col = b * TQ + t;
        int c = min(scnt[tx], CAP);
        g_cnt[col] = c;
        for (int i = 0; i < c; i++) g_cand[(size_t)col * CAP + i] = scand[tx][i];
    }
}

// ---------------------------------------------------------------------------
// Exact fp32 argmax over candidate set. One warp per (b,t) column.
// ---------------------------------------------------------------------------
__global__ void refine(const float* __restrict__ K, const float* __restrict__ Q,
                       float* __restrict__ Mx) {
    const int col = blockIdx.x * 8 + (threadIdx.x >> 5);
    const int lane = threadIdx.x & 31;
    const int b = col >> 10, t = col & 1023;

    const int cnt = min(g_cnt[col], CAP);
    const float* Kb = K + (size_t)b * DD * NK;
    const float* Qb = Q + (size_t)b * DD * TQ;

    int bi;
    if (cnt == 1) {
        bi = g_cand[(size_t)col * CAP];
    } else {
        float bs = -CUDART_INF_F;
        bi = 0x7fffffff;
        for (int c = 0; c < cnt; c++) {
            int n = g_cand[(size_t)col * CAP + c];
            float s = 0.0f;
#pragma unroll
            for (int d = lane; d < DD; d += 32)
                s += Kb[(size_t)d * NK + n] * Qb[(size_t)d * TQ + t];
#pragma unroll
            for (int o = 16; o > 0; o >>= 1)
                s += __shfl_xor_sync(0xFFFFFFFFu, s, o);
            if (s > bs || (s == bs && n < bi)) { bs = s; bi = n; }
        }
    }
    if (lane == 0) Mx[col] = (float)bi;
}

// ---------------------------------------------------------------------------
__global__ void copy_q(const float* __restrict__ Q, float* __restrict__ O) {
    const size_t per = (size_t)DD * TQ;
    const size_t total = (size_t)BB * per;
    size_t i = (size_t)blockIdx.x * blockDim.x + threadIdx.x;
    const size_t stride = (size_t)gridDim.x * blockDim.x;
    for (size_t e = i * 4; e < total; e += stride * 4) {
        size_t b = e / per;
        size_t r = e - b * per;
        float4 v = *(const float4*)&Q[e];
        *(float4*)&O[b * (size_t)(2 * DD) * TQ + per + r] = v;
    }
}

extern "C" void kernel_launch(void* const* d_in, const int* in_sizes, int n_in,
                              void* d_out, int out_size) {
    const float* K = (const float*)d_in[0];
    const float* V = (const float*)d_in[1];
    const float* Q = (const float*)d_in[2];
    float* out = (float*)d_out;

    float* R = out;
    float* A = out + (size_t)BB * 2 * DD * TQ;
    float* MX = A + (size_t)BB * NK * TQ;

    gemm1<<<dim3(TQ / 128, NK / 128, BB), 256>>>(K, Q, A);
    softmax_cand<<<dim3(TQ / 32, BB), dim3(32, 16)>>>(A);
    refine<<<(BB * TQ) / 8, 256>>>(K, Q, MX);
    gemm2<<<dim3(TQ / 128, DD / 128, BB), 256>>>(V, A, R);
    copy_q<<<512, 256>>>(Q, R);
}

// round 7
// speedup vs baseline: 1.0018x; 1.0013x over previous
#include <cuda_runtime.h>
#include <cstdint>
#include <math_constants.h>

#define BB 8
#define DD 256
#define NK 4096
#define TQ 1024
#define SC 0.0625f
#define EPS 0.04f
#define CAP 32

__device__ int g_cnt[BB * TQ];
__device__ int g_cand[BB * TQ * CAP];

// tf32 round-to-nearest of an fp32, returned as float bit pattern
__device__ __forceinline__ float tf32f(float x) {
    uint32_t u;
    asm("cvt.rna.tf32.f32 %0, %1;" : "=r"(u) : "f"(x));
    return __uint_as_float(u);
}

__device__ __forceinline__ void mma8(float* c, const uint32_t* a, const uint32_t* b) {
    asm volatile(
        "mma.sync.aligned.m16n8k8.row.col.f32.tf32.tf32.f32 "
        "{%0,%1,%2,%3}, {%4,%5,%6,%7}, {%8,%9}, {%0,%1,%2,%3};"
        : "+f"(c[0]), "+f"(c[1]), "+f"(c[2]), "+f"(c[3])
        : "r"(a[0]), "r"(a[1]), "r"(a[2]), "r"(a[3]), "r"(b[0]), "r"(b[1]));
}

// ---------------------------------------------------------------------------
// GEMM1: S[n][t] = SC * sum_d K[d][n] * Q[d][t]   (tf32 mma.sync)
// CTA tile 128(n) x 128(t), k-chunk 32 over d. 8 warps: 2(n) x 4(t).
// ---------------------------------------------------------------------------
__global__ void __launch_bounds__(256) gemm1(const float* __restrict__ K,
                                             const float* __restrict__ Q,
                                             float* __restrict__ S) {
    __shared__ float Ks[32][132];   // [d][n]
    __shared__ float Qs[32][132];   // [d][t]

    const int b = blockIdx.z, n0 = blockIdx.y * 128, t0 = blockIdx.x * 128;
    const int tid = threadIdx.x, lane = tid & 31, warp = tid >> 5;
    const int wy = warp >> 2, wx = warp & 3;       // warp tile: 64(n) x 32(t)
    const int tig = lane & 3, grp = lane >> 2;

    const float* Kb = K + (size_t)b * DD * NK;
    const float* Qb = Q + (size_t)b * DD * TQ;

    float acc[4][4][4] = {};
    float4 kreg[4], qreg[4];

#pragma unroll
    for (int p = 0; p < 4; p++) {
        int fl = tid + p * 256, r = fl >> 5, c = (fl & 31) * 4;
        kreg[p] = *(const float4*)&Kb[(size_t)r * NK + n0 + c];
        qreg[p] = *(const float4*)&Qb[(size_t)r * TQ + t0 + c];
    }

    for (int ch = 0; ch < 8; ch++) {
#pragma unroll
        for (int p = 0; p < 4; p++) {
            int fl = tid + p * 256, r = fl >> 5, c = (fl & 31) * 4;
            Ks[r][c + 0] = tf32f(kreg[p].x); Ks[r][c + 1] = tf32f(kreg[p].y);
            Ks[r][c + 2] = tf32f(kreg[p].z); Ks[r][c + 3] = tf32f(kreg[p].w);
            Qs[r][c + 0] = tf32f(qreg[p].x); Qs[r][c + 1] = tf32f(qreg[p].y);
            Qs[r][c + 2] = tf32f(qreg[p].z); Qs[r][c + 3] = tf32f(qreg[p].w);
        }
        __syncthreads();
        if (ch < 7) {
            const int k0 = (ch + 1) * 32;
#pragma unroll
            for (int p = 0; p < 4; p++) {
                int fl = tid + p * 256, r = fl >> 5, c = (fl & 31) * 4;
                kreg[p] = *(const float4*)&Kb[(size_t)(k0 + r) * NK + n0 + c];
                qreg[p] = *(const float4*)&Qb[(size_t)(k0 + r) * TQ + t0 + c];
            }
        }
#pragma unroll
        for (int kk = 0; kk < 4; kk++) {
            uint32_t af[4][4], bf[4][2];
#pragma unroll
            for (int mi = 0; mi < 4; mi++) {
                int rb = wy * 64 + mi * 16 + grp;
                af[mi][0] = __float_as_uint(Ks[kk * 8 + tig][rb]);
                af[mi][1] = __float_as_uint(Ks[kk * 8 + tig][rb + 8]);
                af[mi][2] = __float_as_uint(Ks[kk * 8 + tig + 4][rb]);
                af[mi][3] = __float_as_uint(Ks[kk * 8 + tig + 4][rb + 8]);
            }
#pragma unroll
            for (int nj = 0; nj < 4; nj++) {
                int cb = wx * 32 + nj * 8 + grp;
                bf[nj][0] = __float_as_uint(Qs[kk * 8 + tig][cb]);
                bf[nj][1] = __float_as_uint(Qs[kk * 8 + tig + 4][cb]);
            }
#pragma unroll
            for (int mi = 0; mi < 4; mi++)
#pragma unroll
                for (int nj = 0; nj < 4; nj++)
                    mma8(acc[mi][nj], af[mi], bf[nj]);
        }
        __syncthreads();
    }

    float* Sb = S + (size_t)b * NK * TQ;
#pragma unroll
    for (int mi = 0; mi < 4; mi++)
#pragma unroll
        for (int nj = 0; nj < 4; nj++) {
            int rg = n0 + wy * 64 + mi * 16 + grp;
            int cg = t0 + wx * 32 + nj * 8 + tig * 2;
            float2 v0 = {acc[mi][nj][0] * SC, acc[mi][nj][1] * SC};
            float2 v1 = {acc[mi][nj][2] * SC, acc[mi][nj][3] * SC};
            *(float2*)&Sb[(size_t)rg * TQ + cg] = v0;
            *(float2*)&Sb[(size_t)(rg + 8) * TQ + cg] = v1;
        }
}

// ---------------------------------------------------------------------------
// GEMM2: R[d][t] = sum_n V[d][n] * A[n][t]   (tf32 mma.sync)
// CTA tile 128(d) x 128(t), k-chunk 32 over n.
// ---------------------------------------------------------------------------
__global__ void __launch_bounds__(256) gemm2(const float* __restrict__ V,
                                             const float* __restrict__ A,
                                             float* __restrict__ R) {
    __shared__ float Vs[128][36];   // [d][n]
    __shared__ float As[32][132];   // [n][t]

    const int b = blockIdx.z, d0 = blockIdx.y * 128, t0 = blockIdx.x * 128;
    const int tid = threadIdx.x, lane = tid & 31, warp = tid >> 5;
    const int wy = warp >> 2, wx = warp & 3;
    const int tig = lane & 3, grp = lane >> 2;

    const float* Vb = V + (size_t)b * DD * NK + (size_t)d0 * NK;
    const float* Ab = A + (size_t)b * NK * TQ;

    float acc[4][4][4] = {};
    float4 vreg[4], areg[4];

#pragma unroll
    for (int p = 0; p < 4; p++) {
        int fl = tid + p * 256;
        int rv = fl >> 3, cv = (fl & 7) * 4;
        vreg[p] = *(const float4*)&Vb[(size_t)rv * NK + cv];
        int ra = fl >> 5, ca = (fl & 31) * 4;
        areg[p] = *(const float4*)&Ab[(size_t)ra * TQ + t0 + ca];
    }

    for (int ch = 0; ch < 128; ch++) {
#pragma unroll
        for (int p = 0; p < 4; p++) {
            int fl = tid + p * 256;
            int rv = fl >> 3, cv = (fl & 7) * 4;
            Vs[rv][cv + 0] = tf32f(vreg[p].x); Vs[rv][cv + 1] = tf32f(vreg[p].y);
            Vs[rv][cv + 2] = tf32f(vreg[p].z); Vs[rv][cv + 3] = tf32f(vreg[p].w);
            int ra = fl >> 5, ca = (fl & 31) * 4;
            As[ra][ca + 0] = tf32f(areg[p].x); As[ra][ca + 1] = tf32f(areg[p].y);
            As[ra][ca + 2] = tf32f(areg[p].z); As[ra][ca + 3] = tf32f(areg[p].w);
        }
        __syncthreads();
        if (ch < 127) {
            const int k0 = (ch + 1) * 32;
#pragma unroll
            for (int p = 0; p < 4; p++) {
                int fl = tid + p * 256;
                int rv = fl >> 3, cv = (fl & 7) * 4;
                vreg[p] = *(const float4*)&Vb[(size_t)rv * NK + k0 + cv];
                int ra = fl >> 5, ca = (fl & 31) * 4;
                areg[p] = *(const float4*)&Ab[(size_t)(k0 + ra) * TQ + t0 + ca];
            }
        }
#pragma unroll
        for (int kk = 0; kk < 4; kk++) {
            uint32_t af[4][4], bf[4][2];
#pragma unroll
            for (int mi = 0; mi < 4; mi++) {
                int rb = wy * 64 + mi * 16 + grp;
                af[mi][0] = __float_as_uint(Vs[rb][kk * 8 + tig]);
                af[mi][1] = __float_as_uint(Vs[rb + 8][kk * 8 + tig]);
                af[mi][2] = __float_as_uint(Vs[rb][kk * 8 + tig + 4]);
                af[mi][3] = __float_as_uint(Vs[rb + 8][kk * 8 + tig + 4]);
            }
#pragma unroll
            for (int nj = 0; nj < 4; nj++) {
                int cb = wx * 32 + nj * 8 + grp;
                bf[nj][0] = __float_as_uint(As[kk * 8 + tig][cb]);
                bf[nj][1] = __float_as_uint(As[kk * 8 + tig + 4][cb]);
            }
#pragma unroll
            for (int mi = 0; mi < 4; mi++)
#pragma unroll
                for (int nj = 0; nj < 4; nj++)
                    mma8(acc[mi][nj], af[mi], bf[nj]);
        }
        __syncthreads();
    }

    float* Rb = R + (size_t)b * (2 * DD) * TQ;
#pragma unroll
    for (int mi = 0; mi < 4; mi++)
#pragma unroll
        for (int nj = 0; nj < 4; nj++) {
            int rg = d0 + wy * 64 + mi * 16 + grp;
            int cg = t0 + wx * 32 + nj * 8 + tig * 2;
            float2 v0 = {acc[mi][nj][0], acc[mi][nj][1]};
            float2 v1 = {acc[mi][nj][2], acc[mi][nj][3]};
            *(float2*)&Rb[(size_t)rg * TQ + cg] = v0;
            *(float2*)&Rb[(size_t)(rg + 8) * TQ + cg] = v1;
        }
}

// ---------------------------------------------------------------------------
// Softmax over n per (b,t) column, in place; collects argmax candidates
// (score >= max - EPS) for exact refinement.
// ---------------------------------------------------------------------------
__global__ void softmax_cand(float* __restrict__ A) {
    const int b = blockIdx.y;
    const int tx = threadIdx.x;      // 0..31 (t lane)
    const int ty = threadIdx.y;      // 0..15 (n partition)
    const int t = blockIdx.x * 32 + tx;

    float* Ab = A + (size_t)b * NK * TQ + t;

    __shared__ float sm[16][33];
    __shared__ float ss[16][33];
    __shared__ int scnt[32];
    __shared__ int scand[32][CAP];

    if (ty == 0) scnt[tx] = 0;

    float m = -3.0e38f;
#pragma unroll 4
    for (int n = ty; n < NK; n += 16) {
        float s = Ab[(size_t)n * TQ];
        if (s > m) m = s;
    }
    sm[ty][tx] = m;
    __syncthreads();
    if (ty == 0) {
#pragma unroll
        for (int r = 1; r < 16; r++) m = fmaxf(m, sm[r][tx]);
        sm[0][tx] = m;
    }
    __syncthreads();
    m = sm[0][tx];

    const float thr = m - EPS;
    float sum = 0.0f;
#pragma unroll 4
    for (int n = ty; n < NK; n += 16) {
        float s = Ab[(size_t)n * TQ];
        sum += __expf(s - m);
        if (s >= thr) {
            int p = atomicAdd(&scnt[tx], 1);
            if (p < CAP) scand[tx][p] = n;
        }
    }
    ss[ty][tx] = sum;
    __syncthreads();
    if (ty == 0) {
#pragma unroll
        for (int r = 1; r < 16; r++) sum += ss[r][tx];
        ss[0][tx] = 1.0f / sum;
    }
    __syncthreads();
    const float inv = ss[0][tx];

#pragma unroll 4
    for (int n = ty; n < NK; n += 16) {
        size_t o = (size_t)n * TQ;
        Ab[o] = __expf(Ab[o] - m) * inv;
    }

    if (ty == 0) {
        int col = b * TQ + t;
        int c = min(scnt[tx], CAP);
        g_cnt[col] = c;
        for (int i = 0; i < c; i++) g_cand[(size_t)col * CAP + i] = scand[tx][i];
    }
}

// ---------------------------------------------------------------------------
// Exact fp32 argmax over candidate set. One warp per (b,t) column.
// ---------------------------------------------------------------------------
__global__ void refine(const float* __restrict__ K, const float* __restrict__ Q,
                       float* __restrict__ Mx) {
    const int col = blockIdx.x * 8 + (threadIdx.x >> 5);
    const int lane = threadIdx.x & 31;
    const int b = col >> 10, t = col & 1023;

    const int cnt = min(g_cnt[col], CAP);
    const float* Kb = K + (size_t)b * DD * NK;
    const float* Qb = Q + (size_t)b * DD * TQ;

    int bi;
    if (cnt == 1) {
        bi = g_cand[(size_t)col * CAP];
    } else {
        float bs = -CUDART_INF_F;
        bi = 0x7fffffff;
        for (int c = 0; c < cnt; c++) {
            int n = g_cand[(size_t)col * CAP + c];
            float s = 0.0f;
#pragma unroll
            for (int d = lane; d < DD; d += 32)
                s += Kb[(size_t)d * NK + n] * Qb[(size_t)d * TQ + t];
#pragma unroll
            for (int o = 16; o > 0; o >>= 1)
                s += __shfl_xor_sync(0xFFFFFFFFu, s, o);
            if (s > bs || (s == bs && n < bi)) { bs = s; bi = n; }
        }
    }
    if (lane == 0) Mx[col] = (float)bi;
}

// ---------------------------------------------------------------------------
__global__ void copy_q(const float* __restrict__ Q, float* __restrict__ O) {
    const size_t per = (size_t)DD * TQ;
    const size_t total = (size_t)BB * per;
    size_t i = (size_t)blockIdx.x * blockDim.x + threadIdx.x;
    const size_t stride = (size_t)gridDim.x * blockDim.x;
    for (size_t e = i * 4; e < total; e += stride * 4) {
        size_t b = e / per;
        size_t r = e - b * per;
        float4 v = *(const float4*)&Q[e];
        *(float4*)&O[b * (size_t)(2 * DD) * TQ + per + r] = v;
    }
}

extern "C" void kernel_launch(void* const* d_in, const int* in_sizes, int n_in,
                              void* d_out, int out_size) {
    const float* K = (const float*)d_in[0];
    const float* V = (const float*)d_in[1];
    const float* Q = (const float*)d_in[2];
    float* out = (float*)d_out;

    float* R = out;
    float* A = out + (size_t)BB * 2 * DD * TQ;
    float* MX = A + (size_t)BB * NK * TQ;

    gemm1<<<dim3(TQ / 128, NK / 128, BB), 256>>>(K, Q, A);
    softmax_cand<<<dim3(TQ / 32, BB), dim3(32, 16)>>>(A);
    refine<<<(BB * TQ) / 8, 256>>>(K, Q, MX);
    gemm2<<<dim3(TQ / 128, DD / 128, BB), 256>>>(V, A, R);
    copy_q<<<512, 256>>>(Q, R);
}

// round 8
// speedup vs baseline: 1.0032x; 1.0014x over previous
#include <cuda_runtime.h>
#include <cstdint>
#include <math_constants.h>

#define BB 8
#define DD 256
#define NK 4096
#define TQ 1024
#define SC 0.0625f
#define EPS 0.04f
#define CAP 32

__device__ int g_cnt[BB * TQ];
__device__ int g_cand[BB * TQ * CAP];

// tf32 round-to-nearest of an fp32, returned as float bit pattern
__device__ __forceinline__ float tf32f(float x) {
    uint32_t u;
    asm("cvt.rna.tf32.f32 %0, %1;" : "=r"(u) : "f"(x));
    return __uint_as_float(u);
}

__device__ __forceinline__ void mma8(float* c, const uint32_t* a, const uint32_t* b) {
    asm volatile(
        "mma.sync.aligned.m16n8k8.row.col.f32.tf32.tf32.f32 "
        "{%0,%1,%2,%3}, {%4,%5,%6,%7}, {%8,%9}, {%0,%1,%2,%3};"
        : "+f"(c[0]), "+f"(c[1]), "+f"(c[2]), "+f"(c[3])
        : "r"(a[0]), "r"(a[1]), "r"(a[2]), "r"(a[3]), "r"(b[0]), "r"(b[1]));
}

// ---------------------------------------------------------------------------
// GEMM1: S[n][t] = SC * sum_d K[d][n] * Q[d][t]   (tf32 mma.sync)
// CTA tile 128(n) x 128(t), k-chunk 32 over d. 8 warps: 2(n) x 4(t).
// ---------------------------------------------------------------------------
__global__ void __launch_bounds__(256) gemm1(const float* __restrict__ K,
                                             const float* __restrict__ Q,
                                             float* __restrict__ S) {
    __shared__ float Ks[32][132];   // [d][n]
    __shared__ float Qs[32][132];   // [d][t]

    const int b = blockIdx.z, n0 = blockIdx.y * 128, t0 = blockIdx.x * 128;
    const int tid = threadIdx.x, lane = tid & 31, warp = tid >> 5;
    const int wy = warp >> 2, wx = warp & 3;       // warp tile: 64(n) x 32(t)
    const int tig = lane & 3, grp = lane >> 2;

    const float* Kb = K + (size_t)b * DD * NK;
    const float* Qb = Q + (size_t)b * DD * TQ;

    float acc[4][4][4] = {};
    float4 kreg[4], qreg[4];

#pragma unroll
    for (int p = 0; p < 4; p++) {
        int fl = tid + p * 256, r = fl >> 5, c = (fl & 31) * 4;
        kreg[p] = *(const float4*)&Kb[(size_t)r * NK + n0 + c];
        qreg[p] = *(const float4*)&Qb[(size_t)r * TQ + t0 + c];
    }

    for (int ch = 0; ch < 8; ch++) {
#pragma unroll
        for (int p = 0; p < 4; p++) {
            int fl = tid + p * 256, r = fl >> 5, c = (fl & 31) * 4;
            Ks[r][c + 0] = tf32f(kreg[p].x); Ks[r][c + 1] = tf32f(kreg[p].y);
            Ks[r][c + 2] = tf32f(kreg[p].z); Ks[r][c + 3] = tf32f(kreg[p].w);
            Qs[r][c + 0] = tf32f(qreg[p].x); Qs[r][c + 1] = tf32f(qreg[p].y);
            Qs[r][c + 2] = tf32f(qreg[p].z); Qs[r][c + 3] = tf32f(qreg[p].w);
        }
        __syncthreads();
        if (ch < 7) {
            const int k0 = (ch + 1) * 32;
#pragma unroll
            for (int p = 0; p < 4; p++) {
                int fl = tid + p * 256, r = fl >> 5, c = (fl & 31) * 4;
                kreg[p] = *(const float4*)&Kb[(size_t)(k0 + r) * NK + n0 + c];
                qreg[p] = *(const float4*)&Qb[(size_t)(k0 + r) * TQ + t0 + c];
            }
        }
#pragma unroll
        for (int kk = 0; kk < 4; kk++) {
            uint32_t af[4][4], bf[4][2];
#pragma unroll
            for (int mi = 0; mi < 4; mi++) {
                int rb = wy * 64 + mi * 16 + grp;
                af[mi][0] = __float_as_uint(Ks[kk * 8 + tig][rb]);
                af[mi][1] = __float_as_uint(Ks[kk * 8 + tig][rb + 8]);
                af[mi][2] = __float_as_uint(Ks[kk * 8 + tig + 4][rb]);
                af[mi][3] = __float_as_uint(Ks[kk * 8 + tig + 4][rb + 8]);
            }
#pragma unroll
            for (int nj = 0; nj < 4; nj++) {
                int cb = wx * 32 + nj * 8 + grp;
                bf[nj][0] = __float_as_uint(Qs[kk * 8 + tig][cb]);
                bf[nj][1] = __float_as_uint(Qs[kk * 8 + tig + 4][cb]);
            }
#pragma unroll
            for (int mi = 0; mi < 4; mi++)
#pragma unroll
                for (int nj = 0; nj < 4; nj++)
                    mma8(acc[mi][nj], af[mi], bf[nj]);
        }
        __syncthreads();
    }

    float* Sb = S + (size_t)b * NK * TQ;
#pragma unroll
    for (int mi = 0; mi < 4; mi++)
#pragma unroll
        for (int nj = 0; nj < 4; nj++) {
            int rg = n0 + wy * 64 + mi * 16 + grp;
            int cg = t0 + wx * 32 + nj * 8 + tig * 2;
            float2 v0 = {acc[mi][nj][0] * SC, acc[mi][nj][1] * SC};
            float2 v1 = {acc[mi][nj][2] * SC, acc[mi][nj][3] * SC};
            *(float2*)&Sb[(size_t)rg * TQ + cg] = v0;
            *(float2*)&Sb[(size_t)(rg + 8) * TQ + cg] = v1;
        }
}

// ---------------------------------------------------------------------------
// GEMM2: R[d][t] = sum_n V[d][n] * A[n][t]   (tf32 mma.sync)
// CTA tile 128(d) x 128(t), k-chunk 32 over n.
// ---------------------------------------------------------------------------
__global__ void __launch_bounds__(256) gemm2(const float* __restrict__ V,
                                             const float* __restrict__ A,
                                             float* __restrict__ R) {
    __shared__ float Vs[128][36];   // [d][n]
    __shared__ float As[32][132];   // [n][t]

    const int b = blockIdx.z, d0 = blockIdx.y * 128, t0 = blockIdx.x * 128;
    const int tid = threadIdx.x, lane = tid & 31, warp = tid >> 5;
    const int wy = warp >> 2, wx = warp & 3;
    const int tig = lane & 3, grp = lane >> 2;

    const float* Vb = V + (size_t)b * DD * NK + (size_t)d0 * NK;
    const float* Ab = A + (size_t)b * NK * TQ;

    float acc[4][4][4] = {};
    float4 vreg[4], areg[4];

#pragma unroll
    for (int p = 0; p < 4; p++) {
        int fl = tid + p * 256;
        int rv = fl >> 3, cv = (fl & 7) * 4;
        vreg[p] = *(const float4*)&Vb[(size_t)rv * NK + cv];
        int ra = fl >> 5, ca = (fl & 31) * 4;
        areg[p] = *(const float4*)&Ab[(size_t)ra * TQ + t0 + ca];
    }

    for (int ch = 0; ch < 128; ch++) {
#pragma unroll
        for (int p = 0; p < 4; p++) {
            int fl = tid + p * 256;
            int rv = fl >> 3, cv = (fl & 7) * 4;
            Vs[rv][cv + 0] = tf32f(vreg[p].x); Vs[rv][cv + 1] = tf32f(vreg[p].y);
            Vs[rv][cv + 2] = tf32f(vreg[p].z); Vs[rv][cv + 3] = tf32f(vreg[p].w);
            int ra = fl >> 5, ca = (fl & 31) * 4;
            As[ra][ca + 0] = tf32f(areg[p].x); As[ra][ca + 1] = tf32f(areg[p].y);
            As[ra][ca + 2] = tf32f(areg[p].z); As[ra][ca + 3] = tf32f(areg[p].w);
        }
        __syncthreads();
        if (ch < 127) {
            const int k0 = (ch + 1) * 32;
#pragma unroll
            for (int p = 0; p < 4; p++) {
                int fl = tid + p * 256;
                int rv = fl >> 3, cv = (fl & 7) * 4;
                vreg[p] = *(const float4*)&Vb[(size_t)rv * NK + k0 + cv];
                int ra = fl >> 5, ca = (fl & 31) * 4;
                areg[p] = *(const float4*)&Ab[(size_t)(k0 + ra) * TQ + t0 + ca];
            }
        }
#pragma unroll
        for (int kk = 0; kk < 4; kk++) {
            uint32_t af[4][4], bf[4][2];
#pragma unroll
            for (int mi = 0; mi < 4; mi++) {
                int rb = wy * 64 + mi * 16 + grp;
                af[mi][0] = __float_as_uint(Vs[rb][kk * 8 + tig]);
                af[mi][1] = __float_as_uint(Vs[rb + 8][kk * 8 + tig]);
                af[mi][2] = __float_as_uint(Vs[rb][kk * 8 + tig + 4]);
                af[mi][3] = __float_as_uint(Vs[rb + 8][kk * 8 + tig + 4]);
            }
#pragma unroll
            for (int nj = 0; nj < 4; nj++) {
                int cb = wx * 32 + nj * 8 + grp;
                bf[nj][0] = __float_as_uint(As[kk * 8 + tig][cb]);
                bf[nj][1] = __float_as_uint(As[kk * 8 + tig + 4][cb]);
            }
#pragma unroll
            for (int mi = 0; mi < 4; mi++)
#pragma unroll
                for (int nj = 0; nj < 4; nj++)
                    mma8(acc[mi][nj], af[mi], bf[nj]);
        }
        __syncthreads();
    }

    float* Rb = R + (size_t)b * (2 * DD) * TQ;
#pragma unroll
    for (int mi = 0; mi < 4; mi++)
#pragma unroll
        for (int nj = 0; nj < 4; nj++) {
            int rg = d0 + wy * 64 + mi * 16 + grp;
            int cg = t0 + wx * 32 + nj * 8 + tig * 2;
            float2 v0 = {acc[mi][nj][0], acc[mi][nj][1]};
            float2 v1 = {acc[mi][nj][2], acc[mi][nj][3]};
            *(float2*)&Rb[(size_t)rg * TQ + cg] = v0;
            *(float2*)&Rb[(size_t)(rg + 8) * TQ + cg] = v1;
        }
}

// ---------------------------------------------------------------------------
// Softmax over n per (b,t) column, in place; collects argmax candidates
// (score >= max - EPS) for exact refinement.
// ---------------------------------------------------------------------------
__global__ void softmax_cand(float* __restrict__ A) {
    const int b = blockIdx.y;
    const int tx = threadIdx.x;      // 0..31 (t lane)
    const int ty = threadIdx.y;      // 0..15 (n partition)
    const int t = blockIdx.x * 32 + tx;

    float* Ab = A + (size_t)b * NK * TQ + t;

    __shared__ float sm[16][33];
    __shared__ float ss[16][33];
    __shared__ int scnt[32];
    __shared__ int scand[32][CAP];

    if (ty == 0) scnt[tx] = 0;

    float m = -3.0e38f;
#pragma unroll 4
    for (int n = ty; n < NK; n += 16) {
        float s = Ab[(size_t)n * TQ];
        if (s > m) m = s;
    }
    sm[ty][tx] = m;
    __syncthreads();
    if (ty == 0) {
#pragma unroll
        for (int r = 1; r < 16; r++) m = fmaxf(m, sm[r][tx]);
        sm[0][tx] = m;
    }
    __syncthreads();
    m = sm[0][tx];

    const float thr = m - EPS;
    float sum = 0.0f;
#pragma unroll 4
    for (int n = ty; n < NK; n += 16) {
        float s = Ab[(size_t)n * TQ];
        sum += __expf(s - m);
        if (s >= thr) {
            int p = atomicAdd(&scnt[tx], 1);
            if (p < CAP) scand[tx][p] = n;
        }
    }
    ss[ty][tx] = sum;
    __syncthreads();
    if (ty == 0) {
#pragma unroll
        for (int r = 1; r < 16; r++) sum += ss[r][tx];
        ss[0][tx] = 1.0f / sum;
    }
    __syncthreads();
    const float inv = ss[0][tx];

#pragma unroll 4
    for (int n = ty; n < NK; n += 16) {
        size_t o = (size_t)n * TQ;
        Ab[o] = __expf(Ab[o] - m) * inv;
    }

    if (ty == 0) {
        int col = b * TQ + t;
        int c = min(scnt[tx], CAP);
        g_cnt[col] = c;
        for (int i = 0; i < c; i++) g_cand[(size_t)col * CAP + i] = scand[tx][i];
    }
}

// ---------------------------------------------------------------------------
// Exact fp32 argmax over candidate set. One warp per (b,t) column.
// ---------------------------------------------------------------------------
__global__ void refine(const float* __restrict__ K, const float* __restrict__ Q,
                       float* __restrict__ Mx) {
    const int col = blockIdx.x * 8 + (threadIdx.x >> 5);
    const int lane = threadIdx.x & 31;
    const int b = col >> 10, t = col & 1023;

    const int cnt = min(g_cnt[col], CAP);
    const float* Kb = K + (size_t)b * DD * NK;
    const float* Qb = Q + (size_t)b * DD * TQ;

    int bi;
    if (cnt == 1) {
        bi = g_cand[(size_t)col * CAP];
    } else {
        float bs = -CUDART_INF_F;
        bi = 0x7fffffff;
        for (int c = 0; c < cnt; c++) {
            int n = g_cand[(size_t)col * CAP + c];
            float s = 0.0f;
#pragma unroll
            for (int d = lane; d < DD; d += 32)
                s += Kb[(size_t)d * NK + n] * Qb[(size_t)d * TQ + t];
#pragma unroll
            for (int o = 16; o > 0; o >>= 1)
                s += __shfl_xor_sync(0xFFFFFFFFu, s, o);
            if (s > bs || (s == bs && n < bi)) { bs = s; bi = n; }
        }
    }
    if (lane == 0) Mx[col] = (float)bi;
}

// ---------------------------------------------------------------------------
__global__ void copy_q(const float* __restrict__ Q, float* __restrict__ O) {
    const size_t per = (size_t)DD * TQ;
    const size_t total = (size_t)BB * per;
    size_t i = (size_t)blockIdx.x * blockDim.x + threadIdx.x;
    const size_t stride = (size_t)gridDim.x * blockDim.x;
    for (size_t e = i * 4; e < total; e += stride * 4) {
        size_t b = e / per;
        size_t r = e - b * per;
        float4 v = *(const float4*)&Q[e];
        *(float4*)&O[b * (size_t)(2 * DD) * TQ + per + r] = v;
    }
}

extern "C" void kernel_launch(void* const* d_in, const int* in_sizes, int n_in,
                              void* d_out, int out_size) {
    const float* K = (const float*)d_in[0];
    const float* V = (const float*)d_in[1];
    const float* Q = (const float*)d_in[2];
    float* out = (float*)d_out;

    float* R = out;
    float* A = out + (size_t)BB * 2 * DD * TQ;
    float* MX = A + (size_t)BB * NK * TQ;

    gemm1<<<dim3(TQ / 128, NK / 128, BB), 256>>>(K, Q, A);
    softmax_cand<<<dim3(TQ / 32, BB), dim3(32, 16)>>>(A);
    refine<<<(BB * TQ) / 8, 256>>>(K, Q, MX);
    gemm2<<<dim3(TQ / 128, DD / 128, BB), 256>>>(V, A, R);
    copy_q<<<512, 256>>>(Q, R);
}